// round 16
// baseline (speedup 1.0000x reference)
#include <cuda_runtime.h>
#include <cuda_fp16.h>
#include <math.h>
#include <stdint.h>

// Problem dims (fixed by the reference)
#define MTOK   4096
#define DMODEL 1024
#define DFF    4096
#define NHEAD  16
#define HDIM   64
#define SEQ    1024
#define BATCH  4

// ---------------- scratch (device-static; no runtime allocation) ------------
__device__ __half g_h [MTOK * DMODEL];
__device__ __half g_q [MTOK * DMODEL];
__device__ __half g_k [MTOK * DMODEL];
__device__ __half g_v [MTOK * DMODEL];
__device__ __half g_o [MTOK * DMODEL];
__device__ float  g_x2[MTOK * DMODEL];
__device__ __half g_h2[MTOK * DMODEL];
__device__ __half g_a [MTOK * DFF];
// fp16 weights, SAME [K][N] layout as the fp32 originals (no transpose)
__device__ __half g_whq   [DMODEL * DMODEL];
__device__ __half g_whk   [DMODEL * DMODEL];
__device__ __half g_whv   [DMODEL * DMODEL];
__device__ __half g_who   [DMODEL * DMODEL];
__device__ __half g_whfc  [DMODEL * DFF];
__device__ __half g_whproj[DFF * DMODEL];

// ---------------- helpers ----------------------------------------------------
static __device__ __forceinline__ uint32_t s2u(const void* p) {
    uint32_t a;
    asm("{ .reg .u64 t; cvta.to.shared.u64 t, %1; cvt.u32.u64 %0, t; }"
        : "=r"(a) : "l"(p));
    return a;
}
static __device__ __forceinline__ uint32_t f22u(float a, float b) {
    __half2 h = __floats2half2_rn(a, b);
    return *(uint32_t*)&h;
}
static __device__ __forceinline__ void cp16(uint32_t dst, const void* src) {
    asm volatile("cp.async.cg.shared.global [%0], [%1], 16;"
                 :: "r"(dst), "l"(src) : "memory");
}
static __device__ __forceinline__ void cp_commit() {
    asm volatile("cp.async.commit_group;" ::: "memory");
}
static __device__ __forceinline__ void cp_wait1() {
    asm volatile("cp.async.wait_group 1;" ::: "memory");
}
static __device__ __forceinline__ void cp_wait0() {
    asm volatile("cp.async.wait_group 0;" ::: "memory");
}
// PDL controls. launch_dependents is ONLY called after a CTA's final output
// stores: writes issued before it are guaranteed visible to dependent grids.
static __device__ __forceinline__ void gdc_wait() {
    asm volatile("griddepcontrol.wait;" ::: "memory");
}
static __device__ __forceinline__ void gdc_launch() {
    asm volatile("griddepcontrol.launch_dependents;" ::: "memory");
}
static __device__ __forceinline__ void mma_f16(
    float* d, const uint32_t* a, const uint32_t* b)
{
    asm volatile(
        "mma.sync.aligned.m16n8k16.row.col.f32.f16.f16.f32 "
        "{%0,%1,%2,%3}, {%4,%5,%6,%7}, {%8,%9}, {%0,%1,%2,%3};"
        : "+f"(d[0]), "+f"(d[1]), "+f"(d[2]), "+f"(d[3])
        : "r"(a[0]), "r"(a[1]), "r"(a[2]), "r"(a[3]), "r"(b[0]), "r"(b[1]));
}
static __device__ __forceinline__ void ldsm_x4(
    uint32_t& r0, uint32_t& r1, uint32_t& r2, uint32_t& r3, uint32_t addr)
{
    asm volatile("ldmatrix.sync.aligned.m8n8.x4.shared.b16 {%0,%1,%2,%3}, [%4];"
                 : "=r"(r0), "=r"(r1), "=r"(r2), "=r"(r3) : "r"(addr));
}
static __device__ __forceinline__ void ldsm_x4_trans(
    uint32_t& r0, uint32_t& r1, uint32_t& r2, uint32_t& r3, uint32_t addr)
{
    asm volatile("ldmatrix.sync.aligned.m8n8.x4.trans.shared.b16 {%0,%1,%2,%3}, [%4];"
                 : "=r"(r0), "=r"(r1), "=r"(r2), "=r"(r3) : "r"(addr));
}

// ---------------- LayerNorm row body -------------------------------------------
static __device__ __forceinline__ void ln_row(
    const float* __restrict__ x, const float* __restrict__ w,
    const float* __restrict__ b, __half* __restrict__ out, int row)
{
    const int tid = threadIdx.x;
    const float4* xr = (const float4*)(x + (size_t)row * DMODEL);
    float4 v = xr[tid];

    float s  = v.x + v.y + v.z + v.w;
    float ss = v.x*v.x + v.y*v.y + v.z*v.z + v.w*v.w;
    #pragma unroll
    for (int o = 16; o; o >>= 1) {
        s  += __shfl_xor_sync(0xffffffffu, s,  o);
        ss += __shfl_xor_sync(0xffffffffu, ss, o);
    }
    __shared__ float sh_s[8], sh_ss[8];
    int wid = tid >> 5, lane = tid & 31;
    if (lane == 0) { sh_s[wid] = s; sh_ss[wid] = ss; }
    __syncthreads();
    s = 0.f; ss = 0.f;
    #pragma unroll
    for (int i = 0; i < 8; i++) { s += sh_s[i]; ss += sh_ss[i]; }

    const float mu  = s * (1.0f / DMODEL);
    const float var = ss * (1.0f / DMODEL) - mu * mu;
    const float r   = rsqrtf(var + 1e-5f);

    float4 w4 = ((const float4*)w)[tid];
    float4 b4 = ((const float4*)b)[tid];
    uint2 u;
    u.x = f22u((v.x - mu) * r * w4.x + b4.x, (v.y - mu) * r * w4.y + b4.y);
    u.y = f22u((v.z - mu) * r * w4.z + b4.z, (v.w - mu) * r * w4.w + b4.w);
    ((uint2*)(out + (size_t)row * DMODEL))[tid] = u;
}

__global__ void __launch_bounds__(256) ln_kernel(
    const float* __restrict__ x, const float* __restrict__ w,
    const float* __restrict__ b, __half* __restrict__ out)
{
    gdc_wait();                                  // x comes from predecessor
    ln_row(x, w, b, out, blockIdx.x);
}

// ---------------- fused prologue: weight convert + LN1 (one launch) -----------
__global__ void __launch_bounds__(256) prep_kernel(
    const float* __restrict__ Wq, const float* __restrict__ Wk,
    const float* __restrict__ Wv, const float* __restrict__ Wo,
    const float* __restrict__ Wfc, const float* __restrict__ Wproj,
    __half* __restrict__ Hq, __half* __restrict__ Hk,
    __half* __restrict__ Hv, __half* __restrict__ Ho,
    __half* __restrict__ Hfc, __half* __restrict__ Hproj,
    const float* __restrict__ x, const float* __restrict__ ln1_w,
    const float* __restrict__ ln1_b, __half* __restrict__ hout)
{
    int bid = blockIdx.x;
    if (bid >= 3072) {
        ln_row(x, ln1_w, ln1_b, hout, bid - 3072);
        return;
    }
    const float* W; __half* H; int lb;
    if (bid < 1024) {
        int w = bid >> 8; lb = bid & 255;
        if (w == 0)      { W = Wq; H = Hq; }
        else if (w == 1) { W = Wk; H = Hk; }
        else if (w == 2) { W = Wv; H = Hv; }
        else             { W = Wo; H = Ho; }
    } else if (bid < 2048) {
        lb = bid - 1024; W = Wfc;   H = Hfc;
    } else {
        lb = bid - 2048; W = Wproj; H = Hproj;
    }
    const float4* in = (const float4*)(W + (size_t)lb * 4096);
    uint2* outp = (uint2*)(H + (size_t)lb * 4096);
    #pragma unroll
    for (int it = 0; it < 4; it++) {
        int i = it * 256 + threadIdx.x;
        float4 v = in[i];
        uint2 u; u.x = f22u(v.x, v.y); u.y = f22u(v.z, v.w);
        outp[i] = u;
    }
}

// ---------------- fp16 mma.sync GEMM (K-major B, PDL weight prefetch) ----------
enum { EPI_BIAS_H = 0, EPI_BIAS_RES = 1, EPI_BIAS_GELU_H = 2 };

#define HROW 72
#define BROW 136
#define A_BYTES (128 * HROW * 2)                  // 18432
#define B_BYTES (64 * BROW * 2)                   // 17408
#define GSTG_B (A_BYTES + B_BYTES)                // 35840
#define GEMM_SMEM_BYTES (3 * GSTG_B)              // 107520

static __device__ __forceinline__ void fill_A(
    uint32_t sb, int st, const __half* __restrict__ A,
    int bm, int K, int kt, int tid)
{
    const int k0 = kt * 64;
    const uint32_t ab = sb + (uint32_t)st * GSTG_B;
    #pragma unroll
    for (int i = 0; i < 4; i++) {
        int c = tid + i * 256;
        int r = c >> 3, c8 = c & 7;
        cp16(ab + r * (HROW * 2) + c8 * 16, A + (size_t)(bm + r) * K + k0 + c8 * 8);
    }
}
static __device__ __forceinline__ void fill_B(
    uint32_t sb, int st, const __half* __restrict__ W,
    int bn, int ldw, int kt, int tid)
{
    const int k0 = kt * 64;
    const uint32_t bb = sb + (uint32_t)st * GSTG_B + A_BYTES;
    #pragma unroll
    for (int i = 0; i < 4; i++) {
        int c = tid + i * 256;
        int r = c >> 4, c16 = c & 15;
        cp16(bb + r * (BROW * 2) + c16 * 16, W + (size_t)(k0 + r) * ldw + bn + c16 * 8);
    }
}

template <int EPI, bool PREFETCH_B>
__device__ __forceinline__ void gemm_mma_body(
    const __half* __restrict__ A, const __half* __restrict__ W,
    const float* __restrict__ bias, const float* __restrict__ res,
    void* Cv, int K, int ldc)
{
    extern __shared__ char smem[];
    const uint32_t sb = s2u(smem);

    const int tid = threadIdx.x;                 // 256
    const int wid = tid >> 5, lane = tid & 31;
    const int wm = wid & 1, wn = wid >> 1;       // 2 x 4 warps -> warp tile 64x32
    const int lr = lane >> 2, lc = lane & 3;
    const int bm = blockIdx.y * 128, bn = blockIdx.x * 128;

    const uint32_t a_off =
        ((uint32_t)(wm * 64 + (lane & 15)) * HROW + (((uint32_t)lane >> 4) << 3)) * 2;
    const int quad = lane >> 3, li = lane & 7;
    const uint32_t b_loff = (uint32_t)A_BYTES + (uint32_t)(wn * 32) * 2 +
        ((uint32_t)((quad & 1) * 8 + li) * BROW + (uint32_t)(quad >> 1) * 8) * 2;

    float acc[4][4][4];
    #pragma unroll
    for (int mi = 0; mi < 4; mi++)
        #pragma unroll
        for (int ni = 0; ni < 4; ni++)
            #pragma unroll
            for (int e = 0; e < 4; e++) acc[mi][ni][e] = 0.f;

    const int KT = K / 64;
    if (PREFETCH_B) {
        // weights are independent of the predecessor: prefetch before PDL wait
        fill_B(sb, 0, W, bn, ldc, 0, tid);
        fill_B(sb, 1, W, bn, ldc, 1, tid);
        gdc_wait();
        fill_A(sb, 0, A, bm, K, 0, tid);
        cp_commit();                              // group0 = B0 + B1 + A0
        fill_A(sb, 1, A, bm, K, 1, tid);
        cp_commit();                              // group1 = A1
    } else {
        gdc_wait();                               // everything depends on pred
        fill_B(sb, 0, W, bn, ldc, 0, tid);
        fill_A(sb, 0, A, bm, K, 0, tid);
        cp_commit();
        fill_B(sb, 1, W, bn, ldc, 1, tid);
        fill_A(sb, 1, A, bm, K, 1, tid);
        cp_commit();
    }

    for (int kt = 0; kt < KT; kt++) {
        if (kt + 1 < KT) cp_wait1(); else cp_wait0();
        __syncthreads();
        if (kt + 2 < KT) {
            fill_A(sb, (kt + 2) % 3, A, bm, K, kt + 2, tid);
            fill_B(sb, (kt + 2) % 3, W, bn, ldc, kt + 2, tid);
            cp_commit();
        }

        const uint32_t stgb = sb + (uint32_t)(kt % 3) * GSTG_B;
        const uint32_t abase = stgb + a_off;
        const uint32_t bbase = stgb + b_loff;

        #pragma unroll
        for (int j = 0; j < 4; j++) {
            uint32_t af[4][4], bf[4][2];
            #pragma unroll
            for (int mi = 0; mi < 4; mi++)
                ldsm_x4(af[mi][0], af[mi][1], af[mi][2], af[mi][3],
                        abase + mi * (16 * HROW * 2) + j * 32);
            #pragma unroll
            for (int np = 0; np < 2; np++) {
                uint32_t r0, r1, r2, r3;
                ldsm_x4_trans(r0, r1, r2, r3,
                              bbase + (uint32_t)(j * 16 * BROW + np * 16) * 2);
                bf[2 * np][0] = r0; bf[2 * np][1] = r1;
                bf[2 * np + 1][0] = r2; bf[2 * np + 1][1] = r3;
            }
            #pragma unroll
            for (int mi = 0; mi < 4; mi++)
                #pragma unroll
                for (int ni = 0; ni < 4; ni++)
                    mma_f16(acc[mi][ni], af[mi], bf[ni]);
        }
    }

    #pragma unroll
    for (int mi = 0; mi < 4; mi++) {
        const int r = bm + wm * 64 + mi * 16 + lr;
        #pragma unroll
        for (int ni = 0; ni < 4; ni++) {
            const int c = bn + wn * 32 + ni * 8 + 2 * lc;
            const float b0 = bias[c], b1 = bias[c + 1];
            float v00 = acc[mi][ni][0] + b0;
            float v01 = acc[mi][ni][1] + b1;
            float v10 = acc[mi][ni][2] + b0;
            float v11 = acc[mi][ni][3] + b1;
            if (EPI == EPI_BIAS_RES) {
                float* C = (float*)Cv;
                const float2 r0 = *(const float2*)(res + (size_t)r * ldc + c);
                const float2 r1 = *(const float2*)(res + (size_t)(r + 8) * ldc + c);
                float2 o0; o0.x = v00 + r0.x; o0.y = v01 + r0.y;
                float2 o1; o1.x = v10 + r1.x; o1.y = v11 + r1.y;
                *(float2*)(C + (size_t)r * ldc + c) = o0;
                *(float2*)(C + (size_t)(r + 8) * ldc + c) = o1;
            } else {
                if (EPI == EPI_BIAS_GELU_H) {
                    v00 = 0.5f * v00 * (1.0f + erff(v00 * 0.70710678118654752f));
                    v01 = 0.5f * v01 * (1.0f + erff(v01 * 0.70710678118654752f));
                    v10 = 0.5f * v10 * (1.0f + erff(v10 * 0.70710678118654752f));
                    v11 = 0.5f * v11 * (1.0f + erff(v11 * 0.70710678118654752f));
                }
                __half* C = (__half*)Cv;
                *(uint32_t*)(C + (size_t)r * ldc + c)       = f22u(v00, v01);
                *(uint32_t*)(C + (size_t)(r + 8) * ldc + c) = f22u(v10, v11);
            }
        }
    }

    gdc_launch();   // AFTER output stores: writes guaranteed visible to dependents
}

template <int EPI>
__global__ void __launch_bounds__(256, 2) gemm_mma_kernel(
    const __half* __restrict__ A, const __half* __restrict__ W,
    const float* __restrict__ bias, const float* __restrict__ res,
    void* C, int K, int ldc)
{
    gemm_mma_body<EPI, true>(A, W, bias, res, C, K, ldc);
}

__global__ void __launch_bounds__(256, 2) qkv_mma_kernel(
    const __half* __restrict__ A,
    const __half* __restrict__ Wq, const float* __restrict__ bq, __half* __restrict__ Cq,
    const __half* __restrict__ Wk, const float* __restrict__ bk, __half* __restrict__ Ck,
    const __half* __restrict__ Wv, const float* __restrict__ bv, __half* __restrict__ Cv)
{
    const __half* W; const float* bias; __half* C;
    if (blockIdx.z == 0)      { W = Wq; bias = bq; C = Cq; }
    else if (blockIdx.z == 1) { W = Wk; bias = bk; C = Ck; }
    else                      { W = Wv; bias = bv; C = Cv; }
    // weights come from prep (direct predecessor) -> no early prefetch
    gemm_mma_body<EPI_BIAS_H, false>(A, W, bias, nullptr, (void*)C, DMODEL, DMODEL);
}

// ---------------- fp16 tensor-core flash attention ------------------------------
#define AHROW 72
#define ATT_Q_BYTES (64 * AHROW * 2)
#define ATT_KV_STG  (2 * 64 * AHROW * 2)
#define ATT_SMEM_BYTES (ATT_Q_BYTES + 2 * ATT_KV_STG)  // 46080

static __device__ __forceinline__ void attn_kv_fill(
    uint32_t sb, int st, const __half* __restrict__ k,
    const __half* __restrict__ v, size_t base, int k0, int tid)
{
    const uint32_t ks = sb + ATT_Q_BYTES + (uint32_t)st * ATT_KV_STG;
    const uint32_t vs = ks + 64 * AHROW * 2;
    #pragma unroll
    for (int i = 0; i < 4; i++) {
        int c = tid + i * 128;
        int r = c >> 3, c8 = c & 7;
        cp16(ks + r * (AHROW * 2) + c8 * 16,
             k + base + (size_t)(k0 + r) * DMODEL + c8 * 8);
    }
    #pragma unroll
    for (int i = 0; i < 4; i++) {
        int c = tid + i * 128;
        int r = c >> 3, c8 = c & 7;
        cp16(vs + r * (AHROW * 2) + c8 * 16,
             v + base + (size_t)(k0 + r) * DMODEL + c8 * 8);
    }
    cp_commit();
}

__global__ void __launch_bounds__(128, 3) attn_mma_kernel(
    const __half* __restrict__ q, const __half* __restrict__ k,
    const __half* __restrict__ v, __half* __restrict__ o)
{
    extern __shared__ char smem[];
    __half* sh = (__half*)smem;
    const uint32_t sb = s2u(smem);

    const int qt = blockIdx.x, hh = blockIdx.y, b = blockIdx.z;
    const int tid = threadIdx.x;
    const int wid = tid >> 5, lane = tid & 31;
    const int lr = lane >> 2, lc = lane & 3;
    const size_t base = (size_t)b * SEQ * DMODEL + (size_t)hh * HDIM;
    const int q0 = qt * 64;

    gdc_wait();                                  // q/k/v come from qkv GEMM

    attn_kv_fill(sb, 0, k, v, base, 0, tid);
    #pragma unroll
    for (int i = 0; i < 4; i++) {
        int c = tid + i * 128;
        int r = c >> 3, c8 = c & 7;
        cp16(sb + r * (AHROW * 2) + c8 * 16,
             q + base + (size_t)(q0 + r) * DMODEL + c8 * 8);
    }
    cp_commit();
    cp_wait0();
    __syncthreads();

    uint32_t qf[4][4];
    {
        const __half2 sc2 = __half2half2(__float2half(0.125f));
        const __half* Qb = sh + (wid * 16 + lr) * AHROW + 2 * lc;
        #pragma unroll
        for (int j = 0; j < 4; j++) {
            const __half* p = Qb + j * 16;
            __half2 h0 = __hmul2(*(const __half2*)p, sc2);
            __half2 h1 = __hmul2(*(const __half2*)(p + 8 * AHROW), sc2);
            __half2 h2 = __hmul2(*(const __half2*)(p + 8), sc2);
            __half2 h3 = __hmul2(*(const __half2*)(p + 8 * AHROW + 8), sc2);
            qf[j][0] = *(uint32_t*)&h0; qf[j][1] = *(uint32_t*)&h1;
            qf[j][2] = *(uint32_t*)&h2; qf[j][3] = *(uint32_t*)&h3;
        }
    }

    float of[8][4];
    #pragma unroll
    for (int ni = 0; ni < 8; ni++)
        #pragma unroll
        for (int e = 0; e < 4; e++) of[ni][e] = 0.f;
    float l0 = 0.f, l1 = 0.f;

    const int quad = lane >> 3, li = lane & 7;
    const uint32_t loff = (((quad & 1) * 8 + li) * AHROW + (quad >> 1) * 8) * 2;
    const uint32_t koff =
        ((uint32_t)((lane & 7) + ((lane & 16) >> 1)) * AHROW + (lane & 8)) * 2;

    const int NT = SEQ / 64;
    for (int kt = 0; kt < NT; kt++) {
        if (kt + 1 < NT) {
            attn_kv_fill(sb, (kt + 1) & 1, k, v, base, (kt + 1) * 64, tid);
            cp_wait1();
        } else {
            cp_wait0();
        }
        __syncthreads();

        const uint32_t kvb = sb + ATT_Q_BYTES + (kt & 1) * ATT_KV_STG;
        const uint32_t vbase = kvb + 64 * AHROW * 2;

        float sf[8][4];
        #pragma unroll
        for (int ni = 0; ni < 8; ni++)
            #pragma unroll
            for (int e = 0; e < 4; e++) sf[ni][e] = 0.f;

        #pragma unroll
        for (int j = 0; j < 4; j++) {
            #pragma unroll
            for (int p = 0; p < 4; p++) {
                uint32_t b0, b1, b2, b3;
                ldsm_x4(b0, b1, b2, b3,
                        kvb + koff + p * (16 * AHROW * 2) + j * 32);
                uint32_t bA[2] = {b0, b1}, bB[2] = {b2, b3};
                mma_f16(sf[2 * p],     qf[j], bA);
                mma_f16(sf[2 * p + 1], qf[j], bB);
            }
        }

        uint32_t pf[8][2];
        #pragma unroll
        for (int ni = 0; ni < 8; ni++) {
            float p00 = __expf(sf[ni][0] - 8.0f);
            float p01 = __expf(sf[ni][1] - 8.0f);
            float p10 = __expf(sf[ni][2] - 8.0f);
            float p11 = __expf(sf[ni][3] - 8.0f);
            l0 += p00 + p01; l1 += p10 + p11;
            pf[ni][0] = f22u(p00, p01);
            pf[ni][1] = f22u(p10, p11);
        }

        #pragma unroll
        for (int j = 0; j < 4; j++) {
            uint32_t af[4];
            af[0] = pf[2 * j][0];     af[1] = pf[2 * j][1];
            af[2] = pf[2 * j + 1][0]; af[3] = pf[2 * j + 1][1];
            #pragma unroll
            for (int np = 0; np < 4; np++) {
                uint32_t r0, r1, r2, r3;
                ldsm_x4_trans(r0, r1, r2, r3,
                              vbase + (j * 16 * AHROW + np * 16) * 2 + loff);
                uint32_t b01[2] = {r0, r1}, b23[2] = {r2, r3};
                mma_f16(of[2 * np],     af, b01);
                mma_f16(of[2 * np + 1], af, b23);
            }
        }
        __syncthreads();
    }

    l0 += __shfl_xor_sync(0xffffffffu, l0, 1);
    l0 += __shfl_xor_sync(0xffffffffu, l0, 2);
    l1 += __shfl_xor_sync(0xffffffffu, l1, 1);
    l1 += __shfl_xor_sync(0xffffffffu, l1, 2);

    const float i0 = 1.0f / l0, i1 = 1.0f / l1;
    const int r0 = q0 + wid * 16 + lr;
    #pragma unroll
    for (int ni = 0; ni < 8; ni++) {
        const int c = ni * 8 + 2 * lc;
        *(uint32_t*)(o + base + (size_t)r0 * DMODEL + c) =
            f22u(of[ni][0] * i0, of[ni][1] * i0);
        *(uint32_t*)(o + base + (size_t)(r0 + 8) * DMODEL + c) =
            f22u(of[ni][2] * i1, of[ni][3] * i1);
    }

    gdc_launch();   // AFTER o stores: safe for Wo GEMM's A-operand reads
}

// ---------------- launch ---------------------------------------------------------
template <typename... Args>
static void launch_pdl(void (*kern)(Args...), dim3 grid, dim3 block,
                       size_t smem, Args... args)
{
    cudaLaunchConfig_t cfg = {};
    cfg.gridDim = grid;
    cfg.blockDim = block;
    cfg.dynamicSmemBytes = smem;
    cfg.stream = 0;
    cudaLaunchAttribute attr[1];
    attr[0].id = cudaLaunchAttributeProgrammaticStreamSerialization;
    attr[0].val.programmaticStreamSerializationAllowed = 1;
    cfg.attrs = attr;
    cfg.numAttrs = 1;
    cudaLaunchKernelEx(&cfg, kern, args...);
}

extern "C" void kernel_launch(void* const* d_in, const int* in_sizes, int n_in,
                              void* d_out, int out_size)
{
    const float* x      = (const float*)d_in[0];
    const float* ln1_w  = (const float*)d_in[1];
    const float* ln1_b  = (const float*)d_in[2];
    const float* Wq     = (const float*)d_in[3];
    const float* bq     = (const float*)d_in[4];
    const float* Wk     = (const float*)d_in[5];
    const float* bk     = (const float*)d_in[6];
    const float* Wv     = (const float*)d_in[7];
    const float* bv     = (const float*)d_in[8];
    const float* Wo     = (const float*)d_in[9];
    const float* bo     = (const float*)d_in[10];
    const float* ln2_w  = (const float*)d_in[11];
    const float* ln2_b  = (const float*)d_in[12];
    const float* Wfc    = (const float*)d_in[13];
    const float* bfc    = (const float*)d_in[14];
    const float* Wproj  = (const float*)d_in[15];
    const float* bproj  = (const float*)d_in[16];
    float* out = (float*)d_out;

    __half *h, *q, *k, *v, *o, *h2, *a;
    float *x2;
    __half *whq, *whk, *whv, *who, *whfc, *whproj;
    cudaGetSymbolAddress((void**)&h,  g_h);
    cudaGetSymbolAddress((void**)&q,  g_q);
    cudaGetSymbolAddress((void**)&k,  g_k);
    cudaGetSymbolAddress((void**)&v,  g_v);
    cudaGetSymbolAddress((void**)&o,  g_o);
    cudaGetSymbolAddress((void**)&x2, g_x2);
    cudaGetSymbolAddress((void**)&h2, g_h2);
    cudaGetSymbolAddress((void**)&a,  g_a);
    cudaGetSymbolAddress((void**)&whq, g_whq);
    cudaGetSymbolAddress((void**)&whk, g_whk);
    cudaGetSymbolAddress((void**)&whv, g_whv);
    cudaGetSymbolAddress((void**)&who, g_who);
    cudaGetSymbolAddress((void**)&whfc, g_whfc);
    cudaGetSymbolAddress((void**)&whproj, g_whproj);

    cudaFuncSetAttribute(gemm_mma_kernel<EPI_BIAS_RES>,
                         cudaFuncAttributeMaxDynamicSharedMemorySize, GEMM_SMEM_BYTES);
    cudaFuncSetAttribute(gemm_mma_kernel<EPI_BIAS_GELU_H>,
                         cudaFuncAttributeMaxDynamicSharedMemorySize, GEMM_SMEM_BYTES);
    cudaFuncSetAttribute(qkv_mma_kernel,
                         cudaFuncAttributeMaxDynamicSharedMemorySize, GEMM_SMEM_BYTES);
    cudaFuncSetAttribute(attn_mma_kernel,
                         cudaFuncAttributeMaxDynamicSharedMemorySize, ATT_SMEM_BYTES);

    // 0+1. weight convert || LN1 (plain launch; dependents wait on completion)
    prep_kernel<<<7168, 256>>>(Wq, Wk, Wv, Wo, Wfc, Wproj,
                               whq, whk, whv, who, whfc, whproj,
                               x, ln1_w, ln1_b, h);

    // 2. q/k/v (PDL: waits for prep)
    launch_pdl(qkv_mma_kernel, dim3(DMODEL / 128, MTOK / 128, 3), dim3(256),
               (size_t)GEMM_SMEM_BYTES,
               (const __half*)h,
               (const __half*)whq, bq, q,
               (const __half*)whk, bk, k,
               (const __half*)whv, bv, v);

    // 3. attention (PDL)
    launch_pdl(attn_mma_kernel, dim3(SEQ / 64, NHEAD, BATCH), dim3(128),
               (size_t)ATT_SMEM_BYTES,
               (const __half*)q, (const __half*)k, (const __half*)v, o);

    // 4. x2 = x + o @ Wo + bo (PDL, weight prefetch)
    launch_pdl(gemm_mma_kernel<EPI_BIAS_RES>, dim3(DMODEL / 128, MTOK / 128),
               dim3(256), (size_t)GEMM_SMEM_BYTES,
               (const __half*)o, (const __half*)who, bo, (const float*)x,
               (void*)x2, DMODEL, DMODEL);

    // 5. h2 = half(ln2(x2)) (PDL)
    launch_pdl(ln_kernel, dim3(MTOK), dim3(256), (size_t)0,
               (const float*)x2, ln2_w, ln2_b, h2);

    // 6. a = half(gelu(h2 @ Wfc + bfc)) (PDL, weight prefetch)
    launch_pdl(gemm_mma_kernel<EPI_BIAS_GELU_H>, dim3(DFF / 128, MTOK / 128),
               dim3(256), (size_t)GEMM_SMEM_BYTES,
               (const __half*)h2, (const __half*)whfc, bfc, (const float*)nullptr,
               (void*)a, DMODEL, DFF);

    // 7. out = x2 + a @ Wproj + bproj (PDL, weight prefetch)
    launch_pdl(gemm_mma_kernel<EPI_BIAS_RES>, dim3(DMODEL / 128, MTOK / 128),
               dim3(256), (size_t)GEMM_SMEM_BYTES,
               (const __half*)a, (const __half*)whproj, bproj, (const float*)x2,
               (void*)out, DFF, DMODEL);
}

// round 17
// speedup vs baseline: 1.0016x; 1.0016x over previous
#include <cuda_runtime.h>
#include <cuda_fp16.h>
#include <math.h>
#include <stdint.h>

// Problem dims (fixed by the reference)
#define MTOK   4096
#define DMODEL 1024
#define DFF    4096
#define NHEAD  16
#define HDIM   64
#define SEQ    1024
#define BATCH  4

// ---------------- scratch (device-static; no runtime allocation) ------------
__device__ __half g_h [MTOK * DMODEL];
__device__ __half g_q [MTOK * DMODEL];
__device__ __half g_k [MTOK * DMODEL];
__device__ __half g_v [MTOK * DMODEL];
__device__ __half g_o [MTOK * DMODEL];
__device__ float  g_x2[MTOK * DMODEL];
__device__ __half g_h2[MTOK * DMODEL];
__device__ __half g_a [MTOK * DFF];
// fp16 weights, SAME [K][N] layout as the fp32 originals (no transpose)
__device__ __half g_whq   [DMODEL * DMODEL];
__device__ __half g_whk   [DMODEL * DMODEL];
__device__ __half g_whv   [DMODEL * DMODEL];
__device__ __half g_who   [DMODEL * DMODEL];
__device__ __half g_whfc  [DMODEL * DFF];
__device__ __half g_whproj[DFF * DMODEL];

// ---------------- helpers ----------------------------------------------------
static __device__ __forceinline__ uint32_t s2u(const void* p) {
    uint32_t a;
    asm("{ .reg .u64 t; cvta.to.shared.u64 t, %1; cvt.u32.u64 %0, t; }"
        : "=r"(a) : "l"(p));
    return a;
}
static __device__ __forceinline__ uint32_t f22u(float a, float b) {
    __half2 h = __floats2half2_rn(a, b);
    return *(uint32_t*)&h;
}
static __device__ __forceinline__ void cp16(uint32_t dst, const void* src) {
    asm volatile("cp.async.cg.shared.global [%0], [%1], 16;"
                 :: "r"(dst), "l"(src) : "memory");
}
static __device__ __forceinline__ void cp_commit() {
    asm volatile("cp.async.commit_group;" ::: "memory");
}
static __device__ __forceinline__ void cp_wait1() {
    asm volatile("cp.async.wait_group 1;" ::: "memory");
}
static __device__ __forceinline__ void cp_wait0() {
    asm volatile("cp.async.wait_group 0;" ::: "memory");
}
// PDL controls. launch_dependents is ONLY called after a CTA's final output
// stores: writes issued before it are guaranteed visible to dependent grids.
static __device__ __forceinline__ void gdc_wait() {
    asm volatile("griddepcontrol.wait;" ::: "memory");
}
static __device__ __forceinline__ void gdc_launch() {
    asm volatile("griddepcontrol.launch_dependents;" ::: "memory");
}
static __device__ __forceinline__ void mma_f16(
    float* d, const uint32_t* a, const uint32_t* b)
{
    asm volatile(
        "mma.sync.aligned.m16n8k16.row.col.f32.f16.f16.f32 "
        "{%0,%1,%2,%3}, {%4,%5,%6,%7}, {%8,%9}, {%0,%1,%2,%3};"
        : "+f"(d[0]), "+f"(d[1]), "+f"(d[2]), "+f"(d[3])
        : "r"(a[0]), "r"(a[1]), "r"(a[2]), "r"(a[3]), "r"(b[0]), "r"(b[1]));
}
static __device__ __forceinline__ void ldsm_x4(
    uint32_t& r0, uint32_t& r1, uint32_t& r2, uint32_t& r3, uint32_t addr)
{
    asm volatile("ldmatrix.sync.aligned.m8n8.x4.shared.b16 {%0,%1,%2,%3}, [%4];"
                 : "=r"(r0), "=r"(r1), "=r"(r2), "=r"(r3) : "r"(addr));
}
static __device__ __forceinline__ void ldsm_x4_trans(
    uint32_t& r0, uint32_t& r1, uint32_t& r2, uint32_t& r3, uint32_t addr)
{
    asm volatile("ldmatrix.sync.aligned.m8n8.x4.trans.shared.b16 {%0,%1,%2,%3}, [%4];"
                 : "=r"(r0), "=r"(r1), "=r"(r2), "=r"(r3) : "r"(addr));
}

// ---------------- LayerNorm: 2 rows per CTA (MLP overlap, fewer CTAs) ---------
static __device__ __forceinline__ void ln_row2(
    const float* __restrict__ x, const float* __restrict__ w,
    const float* __restrict__ b, __half* __restrict__ out, int row0)
{
    const int tid = threadIdx.x;
    const float4* xr0 = (const float4*)(x + (size_t)row0 * DMODEL);
    const float4* xr1 = (const float4*)(x + (size_t)(row0 + 1) * DMODEL);
    float4 v0 = xr0[tid];
    float4 v1 = xr1[tid];

    float s0  = v0.x + v0.y + v0.z + v0.w;
    float q0  = v0.x*v0.x + v0.y*v0.y + v0.z*v0.z + v0.w*v0.w;
    float s1  = v1.x + v1.y + v1.z + v1.w;
    float q1  = v1.x*v1.x + v1.y*v1.y + v1.z*v1.z + v1.w*v1.w;
    #pragma unroll
    for (int o = 16; o; o >>= 1) {
        s0 += __shfl_xor_sync(0xffffffffu, s0, o);
        q0 += __shfl_xor_sync(0xffffffffu, q0, o);
        s1 += __shfl_xor_sync(0xffffffffu, s1, o);
        q1 += __shfl_xor_sync(0xffffffffu, q1, o);
    }
    __shared__ float sh[4][8];
    int wid = tid >> 5, lane = tid & 31;
    if (lane == 0) { sh[0][wid] = s0; sh[1][wid] = q0; sh[2][wid] = s1; sh[3][wid] = q1; }
    __syncthreads();
    s0 = 0.f; q0 = 0.f; s1 = 0.f; q1 = 0.f;
    #pragma unroll
    for (int i = 0; i < 8; i++) {
        s0 += sh[0][i]; q0 += sh[1][i]; s1 += sh[2][i]; q1 += sh[3][i];
    }

    const float mu0 = s0 * (1.0f / DMODEL);
    const float r0  = rsqrtf(q0 * (1.0f / DMODEL) - mu0 * mu0 + 1e-5f);
    const float mu1 = s1 * (1.0f / DMODEL);
    const float r1  = rsqrtf(q1 * (1.0f / DMODEL) - mu1 * mu1 + 1e-5f);

    float4 w4 = ((const float4*)w)[tid];
    float4 b4 = ((const float4*)b)[tid];
    uint2 u0, u1;
    u0.x = f22u((v0.x - mu0) * r0 * w4.x + b4.x, (v0.y - mu0) * r0 * w4.y + b4.y);
    u0.y = f22u((v0.z - mu0) * r0 * w4.z + b4.z, (v0.w - mu0) * r0 * w4.w + b4.w);
    u1.x = f22u((v1.x - mu1) * r1 * w4.x + b4.x, (v1.y - mu1) * r1 * w4.y + b4.y);
    u1.y = f22u((v1.z - mu1) * r1 * w4.z + b4.z, (v1.w - mu1) * r1 * w4.w + b4.w);
    ((uint2*)(out + (size_t)row0 * DMODEL))[tid] = u0;
    ((uint2*)(out + (size_t)(row0 + 1) * DMODEL))[tid] = u1;
}

__global__ void __launch_bounds__(256) ln_kernel(
    const float* __restrict__ x, const float* __restrict__ w,
    const float* __restrict__ b, __half* __restrict__ out)
{
    gdc_wait();                                  // x comes from predecessor
    ln_row2(x, w, b, out, blockIdx.x * 2);
}

// ---------------- fused prologue: weight convert + LN1 (one launch) -----------
// blocks [0,3072): fp32->fp16 weight convert; [3072,5120): LN1, 2 rows each
__global__ void __launch_bounds__(256) prep_kernel(
    const float* __restrict__ Wq, const float* __restrict__ Wk,
    const float* __restrict__ Wv, const float* __restrict__ Wo,
    const float* __restrict__ Wfc, const float* __restrict__ Wproj,
    __half* __restrict__ Hq, __half* __restrict__ Hk,
    __half* __restrict__ Hv, __half* __restrict__ Ho,
    __half* __restrict__ Hfc, __half* __restrict__ Hproj,
    const float* __restrict__ x, const float* __restrict__ ln1_w,
    const float* __restrict__ ln1_b, __half* __restrict__ hout)
{
    int bid = blockIdx.x;
    if (bid >= 3072) {
        ln_row2(x, ln1_w, ln1_b, hout, (bid - 3072) * 2);
        return;
    }
    const float* W; __half* H; int lb;
    if (bid < 1024) {
        int w = bid >> 8; lb = bid & 255;
        if (w == 0)      { W = Wq; H = Hq; }
        else if (w == 1) { W = Wk; H = Hk; }
        else if (w == 2) { W = Wv; H = Hv; }
        else             { W = Wo; H = Ho; }
    } else if (bid < 2048) {
        lb = bid - 1024; W = Wfc;   H = Hfc;
    } else {
        lb = bid - 2048; W = Wproj; H = Hproj;
    }
    const float4* in = (const float4*)(W + (size_t)lb * 4096);
    uint2* outp = (uint2*)(H + (size_t)lb * 4096);
    #pragma unroll
    for (int it = 0; it < 4; it++) {
        int i = it * 256 + threadIdx.x;
        float4 v = in[i];
        uint2 u; u.x = f22u(v.x, v.y); u.y = f22u(v.z, v.w);
        outp[i] = u;
    }
}

// ---------------- fp16 mma.sync GEMM (K-major B, PDL weight prefetch) ----------
enum { EPI_BIAS_H = 0, EPI_BIAS_RES = 1, EPI_BIAS_GELU_H = 2 };

#define HROW 72
#define BROW 136
#define A_BYTES (128 * HROW * 2)                  // 18432
#define B_BYTES (64 * BROW * 2)                   // 17408
#define GSTG_B (A_BYTES + B_BYTES)                // 35840
#define GEMM_SMEM_BYTES (3 * GSTG_B)              // 107520

static __device__ __forceinline__ void fill_A(
    uint32_t sb, int st, const __half* __restrict__ A,
    int bm, int K, int kt, int tid)
{
    const int k0 = kt * 64;
    const uint32_t ab = sb + (uint32_t)st * GSTG_B;
    #pragma unroll
    for (int i = 0; i < 4; i++) {
        int c = tid + i * 256;
        int r = c >> 3, c8 = c & 7;
        cp16(ab + r * (HROW * 2) + c8 * 16, A + (size_t)(bm + r) * K + k0 + c8 * 8);
    }
}
static __device__ __forceinline__ void fill_B(
    uint32_t sb, int st, const __half* __restrict__ W,
    int bn, int ldw, int kt, int tid)
{
    const int k0 = kt * 64;
    const uint32_t bb = sb + (uint32_t)st * GSTG_B + A_BYTES;
    #pragma unroll
    for (int i = 0; i < 4; i++) {
        int c = tid + i * 256;
        int r = c >> 4, c16 = c & 15;
        cp16(bb + r * (BROW * 2) + c16 * 16, W + (size_t)(k0 + r) * ldw + bn + c16 * 8);
    }
}

template <int EPI, bool PREFETCH_B>
__device__ __forceinline__ void gemm_mma_body(
    const __half* __restrict__ A, const __half* __restrict__ W,
    const float* __restrict__ bias, const float* __restrict__ res,
    void* Cv, int K, int ldc)
{
    extern __shared__ char smem[];
    const uint32_t sb = s2u(smem);

    const int tid = threadIdx.x;                 // 256
    const int wid = tid >> 5, lane = tid & 31;
    const int wm = wid & 1, wn = wid >> 1;       // 2 x 4 warps -> warp tile 64x32
    const int lr = lane >> 2, lc = lane & 3;
    const int bm = blockIdx.y * 128, bn = blockIdx.x * 128;

    const uint32_t a_off =
        ((uint32_t)(wm * 64 + (lane & 15)) * HROW + (((uint32_t)lane >> 4) << 3)) * 2;
    const int quad = lane >> 3, li = lane & 7;
    const uint32_t b_loff = (uint32_t)A_BYTES + (uint32_t)(wn * 32) * 2 +
        ((uint32_t)((quad & 1) * 8 + li) * BROW + (uint32_t)(quad >> 1) * 8) * 2;

    float acc[4][4][4];
    #pragma unroll
    for (int mi = 0; mi < 4; mi++)
        #pragma unroll
        for (int ni = 0; ni < 4; ni++)
            #pragma unroll
            for (int e = 0; e < 4; e++) acc[mi][ni][e] = 0.f;

    const int KT = K / 64;
    if (PREFETCH_B) {
        // weights are independent of the predecessor: prefetch before PDL wait
        fill_B(sb, 0, W, bn, ldc, 0, tid);
        fill_B(sb, 1, W, bn, ldc, 1, tid);
        gdc_wait();
        fill_A(sb, 0, A, bm, K, 0, tid);
        cp_commit();                              // group0 = B0 + B1 + A0
        fill_A(sb, 1, A, bm, K, 1, tid);
        cp_commit();                              // group1 = A1
    } else {
        gdc_wait();                               // everything depends on pred
        fill_B(sb, 0, W, bn, ldc, 0, tid);
        fill_A(sb, 0, A, bm, K, 0, tid);
        cp_commit();
        fill_B(sb, 1, W, bn, ldc, 1, tid);
        fill_A(sb, 1, A, bm, K, 1, tid);
        cp_commit();
    }

    for (int kt = 0; kt < KT; kt++) {
        if (kt + 1 < KT) cp_wait1(); else cp_wait0();
        __syncthreads();
        if (kt + 2 < KT) {
            fill_A(sb, (kt + 2) % 3, A, bm, K, kt + 2, tid);
            fill_B(sb, (kt + 2) % 3, W, bn, ldc, kt + 2, tid);
            cp_commit();
        }

        const uint32_t stgb = sb + (uint32_t)(kt % 3) * GSTG_B;
        const uint32_t abase = stgb + a_off;
        const uint32_t bbase = stgb + b_loff;

        #pragma unroll
        for (int j = 0; j < 4; j++) {
            uint32_t af[4][4], bf[4][2];
            #pragma unroll
            for (int mi = 0; mi < 4; mi++)
                ldsm_x4(af[mi][0], af[mi][1], af[mi][2], af[mi][3],
                        abase + mi * (16 * HROW * 2) + j * 32);
            #pragma unroll
            for (int np = 0; np < 2; np++) {
                uint32_t r0, r1, r2, r3;
                ldsm_x4_trans(r0, r1, r2, r3,
                              bbase + (uint32_t)(j * 16 * BROW + np * 16) * 2);
                bf[2 * np][0] = r0; bf[2 * np][1] = r1;
                bf[2 * np + 1][0] = r2; bf[2 * np + 1][1] = r3;
            }
            #pragma unroll
            for (int mi = 0; mi < 4; mi++)
                #pragma unroll
                for (int ni = 0; ni < 4; ni++)
                    mma_f16(acc[mi][ni], af[mi], bf[ni]);
        }
    }

    #pragma unroll
    for (int mi = 0; mi < 4; mi++) {
        const int r = bm + wm * 64 + mi * 16 + lr;
        #pragma unroll
        for (int ni = 0; ni < 4; ni++) {
            const int c = bn + wn * 32 + ni * 8 + 2 * lc;
            const float b0 = bias[c], b1 = bias[c + 1];
            float v00 = acc[mi][ni][0] + b0;
            float v01 = acc[mi][ni][1] + b1;
            float v10 = acc[mi][ni][2] + b0;
            float v11 = acc[mi][ni][3] + b1;
            if (EPI == EPI_BIAS_RES) {
                float* C = (float*)Cv;
                const float2 r0 = *(const float2*)(res + (size_t)r * ldc + c);
                const float2 r1 = *(const float2*)(res + (size_t)(r + 8) * ldc + c);
                float2 o0; o0.x = v00 + r0.x; o0.y = v01 + r0.y;
                float2 o1; o1.x = v10 + r1.x; o1.y = v11 + r1.y;
                *(float2*)(C + (size_t)r * ldc + c) = o0;
                *(float2*)(C + (size_t)(r + 8) * ldc + c) = o1;
            } else {
                if (EPI == EPI_BIAS_GELU_H) {
                    v00 = 0.5f * v00 * (1.0f + erff(v00 * 0.70710678118654752f));
                    v01 = 0.5f * v01 * (1.0f + erff(v01 * 0.70710678118654752f));
                    v10 = 0.5f * v10 * (1.0f + erff(v10 * 0.70710678118654752f));
                    v11 = 0.5f * v11 * (1.0f + erff(v11 * 0.70710678118654752f));
                }
                __half* C = (__half*)Cv;
                *(uint32_t*)(C + (size_t)r * ldc + c)       = f22u(v00, v01);
                *(uint32_t*)(C + (size_t)(r + 8) * ldc + c) = f22u(v10, v11);
            }
        }
    }

    gdc_launch();   // AFTER output stores: writes guaranteed visible to dependents
}

template <int EPI>
__global__ void __launch_bounds__(256, 2) gemm_mma_kernel(
    const __half* __restrict__ A, const __half* __restrict__ W,
    const float* __restrict__ bias, const float* __restrict__ res,
    void* C, int K, int ldc)
{
    gemm_mma_body<EPI, true>(A, W, bias, res, C, K, ldc);
}

__global__ void __launch_bounds__(256, 2) qkv_mma_kernel(
    const __half* __restrict__ A,
    const __half* __restrict__ Wq, const float* __restrict__ bq, __half* __restrict__ Cq,
    const __half* __restrict__ Wk, const float* __restrict__ bk, __half* __restrict__ Ck,
    const __half* __restrict__ Wv, const float* __restrict__ bv, __half* __restrict__ Cv)
{
    const __half* W; const float* bias; __half* C;
    if (blockIdx.z == 0)      { W = Wq; bias = bq; C = Cq; }
    else if (blockIdx.z == 1) { W = Wk; bias = bk; C = Ck; }
    else                      { W = Wv; bias = bv; C = Cv; }
    // weights come from prep (direct predecessor) -> no early prefetch
    gemm_mma_body<EPI_BIAS_H, false>(A, W, bias, nullptr, (void*)C, DMODEL, DMODEL);
}

// ---------------- fp16 tensor-core flash attention ------------------------------
#define AHROW 72
#define ATT_Q_BYTES (64 * AHROW * 2)
#define ATT_KV_STG  (2 * 64 * AHROW * 2)
#define ATT_SMEM_BYTES (ATT_Q_BYTES + 2 * ATT_KV_STG)  // 46080

static __device__ __forceinline__ void attn_kv_fill(
    uint32_t sb, int st, const __half* __restrict__ k,
    const __half* __restrict__ v, size_t base, int k0, int tid)
{
    const uint32_t ks = sb + ATT_Q_BYTES + (uint32_t)st * ATT_KV_STG;
    const uint32_t vs = ks + 64 * AHROW * 2;
    #pragma unroll
    for (int i = 0; i < 4; i++) {
        int c = tid + i * 128;
        int r = c >> 3, c8 = c & 7;
        cp16(ks + r * (AHROW * 2) + c8 * 16,
             k + base + (size_t)(k0 + r) * DMODEL + c8 * 8);
    }
    #pragma unroll
    for (int i = 0; i < 4; i++) {
        int c = tid + i * 128;
        int r = c >> 3, c8 = c & 7;
        cp16(vs + r * (AHROW * 2) + c8 * 16,
             v + base + (size_t)(k0 + r) * DMODEL + c8 * 8);
    }
    cp_commit();
}

__global__ void __launch_bounds__(128, 3) attn_mma_kernel(
    const __half* __restrict__ q, const __half* __restrict__ k,
    const __half* __restrict__ v, __half* __restrict__ o)
{
    extern __shared__ char smem[];
    __half* sh = (__half*)smem;
    const uint32_t sb = s2u(smem);

    const int qt = blockIdx.x, hh = blockIdx.y, b = blockIdx.z;
    const int tid = threadIdx.x;
    const int wid = tid >> 5, lane = tid & 31;
    const int lr = lane >> 2, lc = lane & 3;
    const size_t base = (size_t)b * SEQ * DMODEL + (size_t)hh * HDIM;
    const int q0 = qt * 64;

    gdc_wait();                                  // q/k/v come from qkv GEMM

    attn_kv_fill(sb, 0, k, v, base, 0, tid);
    #pragma unroll
    for (int i = 0; i < 4; i++) {
        int c = tid + i * 128;
        int r = c >> 3, c8 = c & 7;
        cp16(sb + r * (AHROW * 2) + c8 * 16,
             q + base + (size_t)(q0 + r) * DMODEL + c8 * 8);
    }
    cp_commit();
    cp_wait0();
    __syncthreads();

    uint32_t qf[4][4];
    {
        const __half2 sc2 = __half2half2(__float2half(0.125f));
        const __half* Qb = sh + (wid * 16 + lr) * AHROW + 2 * lc;
        #pragma unroll
        for (int j = 0; j < 4; j++) {
            const __half* p = Qb + j * 16;
            __half2 h0 = __hmul2(*(const __half2*)p, sc2);
            __half2 h1 = __hmul2(*(const __half2*)(p + 8 * AHROW), sc2);
            __half2 h2 = __hmul2(*(const __half2*)(p + 8), sc2);
            __half2 h3 = __hmul2(*(const __half2*)(p + 8 * AHROW + 8), sc2);
            qf[j][0] = *(uint32_t*)&h0; qf[j][1] = *(uint32_t*)&h1;
            qf[j][2] = *(uint32_t*)&h2; qf[j][3] = *(uint32_t*)&h3;
        }
    }

    float of[8][4];
    #pragma unroll
    for (int ni = 0; ni < 8; ni++)
        #pragma unroll
        for (int e = 0; e < 4; e++) of[ni][e] = 0.f;
    float l0 = 0.f, l1 = 0.f;

    const int quad = lane >> 3, li = lane & 7;
    const uint32_t loff = (((quad & 1) * 8 + li) * AHROW + (quad >> 1) * 8) * 2;
    const uint32_t koff =
        ((uint32_t)((lane & 7) + ((lane & 16) >> 1)) * AHROW + (lane & 8)) * 2;

    const int NT = SEQ / 64;
    for (int kt = 0; kt < NT; kt++) {
        if (kt + 1 < NT) {
            attn_kv_fill(sb, (kt + 1) & 1, k, v, base, (kt + 1) * 64, tid);
            cp_wait1();
        } else {
            cp_wait0();
        }
        __syncthreads();

        const uint32_t kvb = sb + ATT_Q_BYTES + (kt & 1) * ATT_KV_STG;
        const uint32_t vbase = kvb + 64 * AHROW * 2;

        float sf[8][4];
        #pragma unroll
        for (int ni = 0; ni < 8; ni++)
            #pragma unroll
            for (int e = 0; e < 4; e++) sf[ni][e] = 0.f;

        #pragma unroll
        for (int j = 0; j < 4; j++) {
            #pragma unroll
            for (int p = 0; p < 4; p++) {
                uint32_t b0, b1, b2, b3;
                ldsm_x4(b0, b1, b2, b3,
                        kvb + koff + p * (16 * AHROW * 2) + j * 32);
                uint32_t bA[2] = {b0, b1}, bB[2] = {b2, b3};
                mma_f16(sf[2 * p],     qf[j], bA);
                mma_f16(sf[2 * p + 1], qf[j], bB);
            }
        }

        uint32_t pf[8][2];
        #pragma unroll
        for (int ni = 0; ni < 8; ni++) {
            float p00 = __expf(sf[ni][0] - 8.0f);
            float p01 = __expf(sf[ni][1] - 8.0f);
            float p10 = __expf(sf[ni][2] - 8.0f);
            float p11 = __expf(sf[ni][3] - 8.0f);
            l0 += p00 + p01; l1 += p10 + p11;
            pf[ni][0] = f22u(p00, p01);
            pf[ni][1] = f22u(p10, p11);
        }

        #pragma unroll
        for (int j = 0; j < 4; j++) {
            uint32_t af[4];
            af[0] = pf[2 * j][0];     af[1] = pf[2 * j][1];
            af[2] = pf[2 * j + 1][0]; af[3] = pf[2 * j + 1][1];
            #pragma unroll
            for (int np = 0; np < 4; np++) {
                uint32_t r0, r1, r2, r3;
                ldsm_x4_trans(r0, r1, r2, r3,
                              vbase + (j * 16 * AHROW + np * 16) * 2 + loff);
                uint32_t b01[2] = {r0, r1}, b23[2] = {r2, r3};
                mma_f16(of[2 * np],     af, b01);
                mma_f16(of[2 * np + 1], af, b23);
            }
        }
        __syncthreads();
    }

    l0 += __shfl_xor_sync(0xffffffffu, l0, 1);
    l0 += __shfl_xor_sync(0xffffffffu, l0, 2);
    l1 += __shfl_xor_sync(0xffffffffu, l1, 1);
    l1 += __shfl_xor_sync(0xffffffffu, l1, 2);

    const float i0 = 1.0f / l0, i1 = 1.0f / l1;
    const int r0 = q0 + wid * 16 + lr;
    #pragma unroll
    for (int ni = 0; ni < 8; ni++) {
        const int c = ni * 8 + 2 * lc;
        *(uint32_t*)(o + base + (size_t)r0 * DMODEL + c) =
            f22u(of[ni][0] * i0, of[ni][1] * i0);
        *(uint32_t*)(o + base + (size_t)(r0 + 8) * DMODEL + c) =
            f22u(of[ni][2] * i1, of[ni][3] * i1);
    }

    gdc_launch();   // AFTER o stores: safe for Wo GEMM's A-operand reads
}

// ---------------- launch ---------------------------------------------------------
template <typename... Args>
static void launch_pdl(void (*kern)(Args...), dim3 grid, dim3 block,
                       size_t smem, Args... args)
{
    cudaLaunchConfig_t cfg = {};
    cfg.gridDim = grid;
    cfg.blockDim = block;
    cfg.dynamicSmemBytes = smem;
    cfg.stream = 0;
    cudaLaunchAttribute attr[1];
    attr[0].id = cudaLaunchAttributeProgrammaticStreamSerialization;
    attr[0].val.programmaticStreamSerializationAllowed = 1;
    cfg.attrs = attr;
    cfg.numAttrs = 1;
    cudaLaunchKernelEx(&cfg, kern, args...);
}

extern "C" void kernel_launch(void* const* d_in, const int* in_sizes, int n_in,
                              void* d_out, int out_size)
{
    const float* x      = (const float*)d_in[0];
    const float* ln1_w  = (const float*)d_in[1];
    const float* ln1_b  = (const float*)d_in[2];
    const float* Wq     = (const float*)d_in[3];
    const float* bq     = (const float*)d_in[4];
    const float* Wk     = (const float*)d_in[5];
    const float* bk     = (const float*)d_in[6];
    const float* Wv     = (const float*)d_in[7];
    const float* bv     = (const float*)d_in[8];
    const float* Wo     = (const float*)d_in[9];
    const float* bo     = (const float*)d_in[10];
    const float* ln2_w  = (const float*)d_in[11];
    const float* ln2_b  = (const float*)d_in[12];
    const float* Wfc    = (const float*)d_in[13];
    const float* bfc    = (const float*)d_in[14];
    const float* Wproj  = (const float*)d_in[15];
    const float* bproj  = (const float*)d_in[16];
    float* out = (float*)d_out;

    __half *h, *q, *k, *v, *o, *h2, *a;
    float *x2;
    __half *whq, *whk, *whv, *who, *whfc, *whproj;
    cudaGetSymbolAddress((void**)&h,  g_h);
    cudaGetSymbolAddress((void**)&q,  g_q);
    cudaGetSymbolAddress((void**)&k,  g_k);
    cudaGetSymbolAddress((void**)&v,  g_v);
    cudaGetSymbolAddress((void**)&o,  g_o);
    cudaGetSymbolAddress((void**)&x2, g_x2);
    cudaGetSymbolAddress((void**)&h2, g_h2);
    cudaGetSymbolAddress((void**)&a,  g_a);
    cudaGetSymbolAddress((void**)&whq, g_whq);
    cudaGetSymbolAddress((void**)&whk, g_whk);
    cudaGetSymbolAddress((void**)&whv, g_whv);
    cudaGetSymbolAddress((void**)&who, g_who);
    cudaGetSymbolAddress((void**)&whfc, g_whfc);
    cudaGetSymbolAddress((void**)&whproj, g_whproj);

    cudaFuncSetAttribute(gemm_mma_kernel<EPI_BIAS_RES>,
                         cudaFuncAttributeMaxDynamicSharedMemorySize, GEMM_SMEM_BYTES);
    cudaFuncSetAttribute(gemm_mma_kernel<EPI_BIAS_GELU_H>,
                         cudaFuncAttributeMaxDynamicSharedMemorySize, GEMM_SMEM_BYTES);
    cudaFuncSetAttribute(qkv_mma_kernel,
                         cudaFuncAttributeMaxDynamicSharedMemorySize, GEMM_SMEM_BYTES);
    cudaFuncSetAttribute(attn_mma_kernel,
                         cudaFuncAttributeMaxDynamicSharedMemorySize, ATT_SMEM_BYTES);

    // 0+1. weight convert (blocks 0-3071) || LN1 2-rows (blocks 3072-5119)
    prep_kernel<<<5120, 256>>>(Wq, Wk, Wv, Wo, Wfc, Wproj,
                               whq, whk, whv, who, whfc, whproj,
                               x, ln1_w, ln1_b, h);

    // 2. q/k/v (PDL: waits for prep)
    launch_pdl(qkv_mma_kernel, dim3(DMODEL / 128, MTOK / 128, 3), dim3(256),
               (size_t)GEMM_SMEM_BYTES,
               (const __half*)h,
               (const __half*)whq, bq, q,
               (const __half*)whk, bk, k,
               (const __half*)whv, bv, v);

    // 3. attention (PDL)
    launch_pdl(attn_mma_kernel, dim3(SEQ / 64, NHEAD, BATCH), dim3(128),
               (size_t)ATT_SMEM_BYTES,
               (const __half*)q, (const __half*)k, (const __half*)v, o);

    // 4. x2 = x + o @ Wo + bo (PDL, weight prefetch)
    launch_pdl(gemm_mma_kernel<EPI_BIAS_RES>, dim3(DMODEL / 128, MTOK / 128),
               dim3(256), (size_t)GEMM_SMEM_BYTES,
               (const __half*)o, (const __half*)who, bo, (const float*)x,
               (void*)x2, DMODEL, DMODEL);

    // 5. h2 = half(ln2(x2)) (PDL, 2 rows per CTA)
    launch_pdl(ln_kernel, dim3(MTOK / 2), dim3(256), (size_t)0,
               (const float*)x2, ln2_w, ln2_b, h2);

    // 6. a = half(gelu(h2 @ Wfc + bfc)) (PDL, weight prefetch)
    launch_pdl(gemm_mma_kernel<EPI_BIAS_GELU_H>, dim3(DFF / 128, MTOK / 128),
               dim3(256), (size_t)GEMM_SMEM_BYTES,
               (const __half*)h2, (const __half*)whfc, bfc, (const float*)nullptr,
               (void*)a, DMODEL, DFF);

    // 7. out = x2 + a @ Wproj + bproj (PDL, weight prefetch)
    launch_pdl(gemm_mma_kernel<EPI_BIAS_RES>, dim3(DMODEL / 128, MTOK / 128),
               dim3(256), (size_t)GEMM_SMEM_BYTES,
               (const __half*)a, (const __half*)whproj, bproj, (const float*)x2,
               (void*)out, DFF, DMODEL);
}